// round 13
// baseline (speedup 1.0000x reference)
#include <cuda_runtime.h>

// Problem constants
#define BC_C   9
#define BC_FR  64
#define BC_T   64
#define BC_P   4
#define BC_E   192
#define BC_NF  16
#define BC_NT  16

#define W_ROW_PAD 68   // 64 floats of W per e-quad + 4 pad -> conflict-free LDS.128

using u64 = unsigned long long;

__device__ __forceinline__ u64 pack2(float lo, float hi) {
    u64 r;
    asm("mov.b64 %0, {%1, %2};" : "=l"(r) : "f"(lo), "f"(hi));
    return r;
}
__device__ __forceinline__ void unpack2(u64 v, float& lo, float& hi) {
    asm("mov.b64 {%0, %1}, %2;" : "=f"(lo), "=f"(hi) : "l"(v));
}
// d = a * b + d  on packed f32x2 (Blackwell FFMA2, rt_SMSP=2 — verified vs ncu)
__device__ __forceinline__ void fma2(u64& d, u64 a, u64 b) {
    asm("fma.rn.f32x2 %0, %1, %2, %0;" : "+l"(d) : "l"(a), "l"(b));
}
// Streaming (evict-first) 16B store: output is write-once, never re-read.
__device__ __forceinline__ void stg_cs(float* p, float4 v) {
    asm volatile("st.global.cs.v4.f32 [%0], {%1, %2, %3, %4};"
                 :: "l"(p), "f"(v.x), "f"(v.y), "f"(v.z), "f"(v.w) : "memory");
}
// cp.async 16B GMEM -> SMEM (LDGSTS)
__device__ __forceinline__ void cp_async16(void* smem_dst, const void* gmem_src) {
    unsigned saddr = (unsigned)__cvta_generic_to_shared(smem_dst);
    asm volatile("cp.async.cg.shared.global [%0], [%1], 16;"
                 :: "r"(saddr), "l"(gmem_src) : "memory");
}

// Grid: (C=9, B, 2 f-halves). Block: 96 threads, FIVE blocks/SM (15 warps in
// five independent contexts). The untried cell in the (unroll x blocks/SM)
// matrix: t-unroll 1 drops ~28 live regs (xp1/acc-b/tp1), bringing the
// estimate (~132) under the 136-reg cap for occupancy 5 WITHOUT spilling
// (round 7's failure was a 96-reg cap — far harsher).
//   q = tid % 48 -> e-quad (e = 4q..4q+3), W for these 4 e rows held in regs
//   g = tid / 48 -> f-group within the half: f = z*8 + g*4 + fi
// Invariants (rounds 4/7/8/10/11): 4-e layout = min L1 work; W-in-regs needs
// 64 regs; barriers cost more than wave transitions; more block contexts at
// fixed warps/SM = better overlap.
__global__ __launch_bounds__(96, 5)
void patch_embed_kernel(const float* __restrict__ x,
                        const float* __restrict__ W,
                        const float* __restrict__ bvec,
                        const float* __restrict__ chEmb,
                        const float* __restrict__ spEmb,
                        const float* __restrict__ timePos,
                        const float* __restrict__ freqPos,
                        const int*   __restrict__ spIdx,
                        float* __restrict__ out)
{
    const int c   = blockIdx.x;   // 0..8
    const int b   = blockIdx.y;   // 0..B-1
    const int z   = blockIdx.z;   // 0..1 (f-half)
    const int tid = threadIdx.x;  // 0..95
    const int q   = tid % 48;
    const int g   = tid / 48;     // 0..1
    const int e0  = q * 4;
    const int f0  = z * 8;        // first f row of this block's half

    __shared__ __align__(16) float xs[(BC_FR / 2) * BC_T];    // 8 KB half-plane
    __shared__ __align__(16) float ws[48 * W_ROW_PAD];        // ~13 KB padded W
    __shared__ __align__(16) float tps[BC_NT * BC_E];         // 12 KB timePos

    // ---- group 1: W + timePos (small, L2-hot after first blocks) ----
    {
        const float4* gw = reinterpret_cast<const float4*>(W);
        #pragma unroll
        for (int j = tid; j < (BC_E * 16) / 4; j += 96) {
            int r   = j >> 4;
            int col = (j & 15) << 2;
            cp_async16(&ws[r * W_ROW_PAD + col], &gw[j]);
        }
        const float4* gt = reinterpret_cast<const float4*>(timePos);
        #pragma unroll
        for (int j = tid; j < (BC_NT * BC_E) / 4; j += 96)
            cp_async16(&reinterpret_cast<float4*>(tps)[j], &gt[j]);
    }
    asm volatile("cp.async.commit_group;" ::: "memory");

    // ---- group 2: this half-plane's 32 x-rows ----
    {
        const float4* gx = reinterpret_cast<const float4*>(
            x + ((size_t)(b * BC_C + c) * BC_FR + (size_t)f0 * BC_P) * BC_T);
        #pragma unroll
        for (int i = tid; i < (BC_FR / 2) * BC_T / 4; i += 96)
            cp_async16(&reinterpret_cast<float4*>(xs)[i], &gx[i]);
    }
    asm volatile("cp.async.commit_group;" ::: "memory");

    // Per-e static bias: b + channel + spatial[spatial_idx[c]] (overlaps copies)
    const int sidx = __ldg(spIdx + c);
    float4 bb = *reinterpret_cast<const float4*>(bvec + e0);
    float4 ce = *reinterpret_cast<const float4*>(chEmb + c * BC_E + e0);
    float4 se = *reinterpret_cast<const float4*>(spEmb + sidx * BC_E + e0);
    float4 bs;
    bs.x = bb.x + ce.x + se.x;
    bs.y = bb.y + ce.y + se.y;
    bs.z = bb.z + ce.z + se.z;
    bs.w = bb.w + ce.w + se.w;

    // Per-f base = static + freq_pos[f], for this thread's 4 f values.
    float4 base[4];
    #pragma unroll
    for (int fi = 0; fi < 4; fi++) {
        const int f = f0 + g * 4 + fi;
        float4 fe = *reinterpret_cast<const float4*>(freqPos + f * BC_E + e0);
        base[fi].x = bs.x + fe.x;
        base[fi].y = bs.y + fe.y;
        base[fi].z = bs.z + fe.z;
        base[fi].w = bs.w + fe.w;
    }

    // Wait group 1 only (W + tp): pull W into regs while x is still in flight.
    asm volatile("cp.async.wait_group 1;" ::: "memory");
    __syncthreads();

    // Pull W for this thread's 4 e rows into regs (conflict-free padded LDS.128).
    u64 w[32];
    #pragma unroll
    for (int i = 0; i < 16; i++) {
        float4 v = *reinterpret_cast<const float4*>(&ws[q * W_ROW_PAD + i * 4]);
        w[2 * i]     = pack2(v.x, v.y);
        w[2 * i + 1] = pack2(v.z, v.w);
    }

    // Now wait for the x tile.
    asm volatile("cp.async.wait_group 0;" ::: "memory");
    __syncthreads();

    float* outp = out + ((size_t)b * (BC_C * BC_NF * BC_NT)
                         + c * (BC_NF * BC_NT)) * BC_E;

    #pragma unroll 1
    for (int t = 0; t < BC_NT; t++) {
        // tp from smem: lane q reads tps[t*192 + 4q] -> conflict-free LDS.128.
        float4 tp = *reinterpret_cast<const float4*>(&tps[t * BC_E + e0]);

        #pragma unroll
        for (int fi = 0; fi < 4; fi++) {
            const int fl = g * 4 + fi;        // local f row within the half
            const int f  = f0 + fl;           // global f (output addressing)

            // Patch x: broadcast LDS (all lanes share (f,t)).
            u64 xp[8];
            #pragma unroll
            for (int u = 0; u < 4; u++) {
                ulonglong2 v = *reinterpret_cast<const ulonglong2*>(
                    &xs[(fl * 4 + u) * BC_T + t * 4]);
                xp[2 * u]     = v.x;
                xp[2 * u + 1] = v.y;
            }

            // Accumulator init {base, tp}: lo/hi halves accumulate independent
            // partial sums; the final lo+hi folds BOTH biases for free.
            u64 a0 = pack2(base[fi].x, tp.x);
            u64 a1 = pack2(base[fi].y, tp.y);
            u64 a2 = pack2(base[fi].z, tp.z);
            u64 a3 = pack2(base[fi].w, tp.w);

            #pragma unroll
            for (int k = 0; k < 8; k++) {
                fma2(a0, xp[k], w[k]);
                fma2(a1, xp[k], w[8 + k]);
                fma2(a2, xp[k], w[16 + k]);
                fma2(a3, xp[k], w[24 + k]);
            }

            float4 r;
            { float lo, hi; unpack2(a0, lo, hi); r.x = lo + hi; }
            { float lo, hi; unpack2(a1, lo, hi); r.y = lo + hi; }
            { float lo, hi; unpack2(a2, lo, hi); r.z = lo + hi; }
            { float lo, hi; unpack2(a3, lo, hi); r.w = lo + hi; }

            stg_cs(outp + (size_t)(f * BC_NT + t) * BC_E + e0, r);
        }
    }
}

extern "C" void kernel_launch(void* const* d_in, const int* in_sizes, int n_in,
                              void* d_out, int out_size)
{
    const float* x    = (const float*)d_in[0];
    const float* W    = (const float*)d_in[1];
    const float* bv   = (const float*)d_in[2];
    const float* ch   = (const float*)d_in[3];
    const float* sp   = (const float*)d_in[4];
    const float* tpos = (const float*)d_in[5];
    const float* fpos = (const float*)d_in[6];
    const int*   sidx = (const int*)d_in[7];
    float* out = (float*)d_out;

    const int Bx = in_sizes[0] / (BC_C * BC_FR * BC_T);

    dim3 grid(BC_C, Bx, 2);
    patch_embed_kernel<<<grid, 96>>>(x, W, bv, ch, sp, tpos, fpos, sidx, out);
}

// round 14
// speedup vs baseline: 1.1238x; 1.1238x over previous
#include <cuda_runtime.h>

// Problem constants
#define BC_C   9
#define BC_FR  64
#define BC_T   64
#define BC_P   4
#define BC_E   192
#define BC_NF  16
#define BC_NT  16

#define W_ROW_PAD 68   // 64 floats of W per e-quad + 4 pad -> conflict-free LDS.128

using u64 = unsigned long long;

__device__ __forceinline__ u64 pack2(float lo, float hi) {
    u64 r;
    asm("mov.b64 %0, {%1, %2};" : "=l"(r) : "f"(lo), "f"(hi));
    return r;
}
__device__ __forceinline__ void unpack2(u64 v, float& lo, float& hi) {
    asm("mov.b64 {%0, %1}, %2;" : "=f"(lo), "=f"(hi) : "l"(v));
}
// d = a * b + d  on packed f32x2 (Blackwell FFMA2, rt_SMSP=2 — verified vs ncu)
__device__ __forceinline__ void fma2(u64& d, u64 a, u64 b) {
    asm("fma.rn.f32x2 %0, %1, %2, %0;" : "+l"(d) : "l"(a), "l"(b));
}
// Streaming (evict-first) 16B store: output is write-once, never re-read.
__device__ __forceinline__ void stg_cs(float* p, float4 v) {
    asm volatile("st.global.cs.v4.f32 [%0], {%1, %2, %3, %4};"
                 :: "l"(p), "f"(v.x), "f"(v.y), "f"(v.z), "f"(v.w) : "memory");
}
// cp.async 16B GMEM -> SMEM (LDGSTS)
__device__ __forceinline__ void cp_async16(void* smem_dst, const void* gmem_src) {
    unsigned saddr = (unsigned)__cvta_generic_to_shared(smem_dst);
    asm volatile("cp.async.cg.shared.global [%0], [%1], 16;"
                 :: "r"(saddr), "l"(gmem_src) : "memory");
}

// Grid: (C=9, B, 2 f-halves). Block: 96 threads, 4 blocks/SM. This is the
// round-12 optimum of the fully-explored (unroll x occupancy) matrix:
//   occ2x192/u2 = 90.9, occ3 = spill 118, occ4x96/u2 = 86.2 (THIS),
//   occ5x96/u1 = 96.7, persistent = 110, e-pair = 101.
//   q = tid % 48 -> e-quad (e = 4q..4q+3), W for these 4 e rows held in regs
//   g = tid / 48 -> f-group within the half: f = z*8 + g*4 + fi
// This round: marching pointers / hoisted bases replace per-store IMAD.WIDE
// address chains (alu-pipe shave; protect-the-win change).
__global__ __launch_bounds__(96, 4)
void patch_embed_kernel(const float* __restrict__ x,
                        const float* __restrict__ W,
                        const float* __restrict__ bvec,
                        const float* __restrict__ chEmb,
                        const float* __restrict__ spEmb,
                        const float* __restrict__ timePos,
                        const float* __restrict__ freqPos,
                        const int*   __restrict__ spIdx,
                        float* __restrict__ out)
{
    const int c   = blockIdx.x;   // 0..8
    const int b   = blockIdx.y;   // 0..B-1
    const int z   = blockIdx.z;   // 0..1 (f-half)
    const int tid = threadIdx.x;  // 0..95
    const int q   = tid % 48;
    const int g   = tid / 48;     // 0..1
    const int e0  = q * 4;
    const int f0  = z * 8;        // first f row of this block's half

    __shared__ __align__(16) float xs[(BC_FR / 2) * BC_T];    // 8 KB half-plane
    __shared__ __align__(16) float ws[48 * W_ROW_PAD];        // ~13 KB padded W
    __shared__ __align__(16) float tps[BC_NT * BC_E];         // 12 KB timePos

    // ---- group 1: W + timePos (small, L2-hot after first blocks) ----
    {
        const float4* gw = reinterpret_cast<const float4*>(W);
        #pragma unroll
        for (int j = tid; j < (BC_E * 16) / 4; j += 96) {
            int r   = j >> 4;
            int col = (j & 15) << 2;
            cp_async16(&ws[r * W_ROW_PAD + col], &gw[j]);
        }
        const float4* gt = reinterpret_cast<const float4*>(timePos);
        #pragma unroll
        for (int j = tid; j < (BC_NT * BC_E) / 4; j += 96)
            cp_async16(&reinterpret_cast<float4*>(tps)[j], &gt[j]);
    }
    asm volatile("cp.async.commit_group;" ::: "memory");

    // ---- group 2: this half-plane's 32 x-rows ----
    {
        const float4* gx = reinterpret_cast<const float4*>(
            x + ((size_t)(b * BC_C + c) * BC_FR + (size_t)f0 * BC_P) * BC_T);
        #pragma unroll
        for (int i = tid; i < (BC_FR / 2) * BC_T / 4; i += 96)
            cp_async16(&reinterpret_cast<float4*>(xs)[i], &gx[i]);
    }
    asm volatile("cp.async.commit_group;" ::: "memory");

    // Per-e static bias: b + channel + spatial[spatial_idx[c]] (overlaps copies)
    const int sidx = __ldg(spIdx + c);
    float4 bb = *reinterpret_cast<const float4*>(bvec + e0);
    float4 ce = *reinterpret_cast<const float4*>(chEmb + c * BC_E + e0);
    float4 se = *reinterpret_cast<const float4*>(spEmb + sidx * BC_E + e0);
    float4 bs;
    bs.x = bb.x + ce.x + se.x;
    bs.y = bb.y + ce.y + se.y;
    bs.z = bb.z + ce.z + se.z;
    bs.w = bb.w + ce.w + se.w;

    // Per-f base = static + freq_pos[f], for this thread's 4 f values.
    float4 base[4];
    #pragma unroll
    for (int fi = 0; fi < 4; fi++) {
        const int f = f0 + g * 4 + fi;
        float4 fe = *reinterpret_cast<const float4*>(freqPos + f * BC_E + e0);
        base[fi].x = bs.x + fe.x;
        base[fi].y = bs.y + fe.y;
        base[fi].z = bs.z + fe.z;
        base[fi].w = bs.w + fe.w;
    }

    // Wait group 1 only (W + tp): pull W into regs while x is still in flight.
    asm volatile("cp.async.wait_group 1;" ::: "memory");
    __syncthreads();

    // Pull W for this thread's 4 e rows into regs (conflict-free padded LDS.128).
    u64 w[32];
    #pragma unroll
    for (int i = 0; i < 16; i++) {
        float4 v = *reinterpret_cast<const float4*>(&ws[q * W_ROW_PAD + i * 4]);
        w[2 * i]     = pack2(v.x, v.y);
        w[2 * i + 1] = pack2(v.z, v.w);
    }

    // Now wait for the x tile.
    asm volatile("cp.async.wait_group 0;" ::: "memory");
    __syncthreads();

    // Hoisted bases for marching-pointer addressing in the hot loop.
    // Thread's first output element: (b,c) plane + f=(f0 + g*4), t=0, e0.
    float* op_base = out + ((size_t)b * (BC_C * BC_NF * BC_NT)
                            + c * (BC_NF * BC_NT)
                            + (size_t)(f0 + g * 4) * BC_NT) * BC_E + e0;
    const float* tp_base = &tps[e0];
    const float* xs_base = &xs[(g * 4) * BC_P * BC_T];   // thread's first f row

    #pragma unroll 1
    for (int t = 0; t < BC_NT; t += 2) {
        // tp from smem (conflict-free LDS.128), marching pointer.
        float4 tp0 = *reinterpret_cast<const float4*>(tp_base);
        float4 tp1 = *reinterpret_cast<const float4*>(tp_base + BC_E);
        tp_base += 2 * BC_E;

        const float* xrow = xs_base + (size_t)(t * 4);   // col offset for this t
        float* op_f = op_base + (size_t)t * BC_E;

        #pragma unroll
        for (int fi = 0; fi < 4; fi++) {
            // Patch x for t and t+1: broadcast LDS (all lanes share (f,t)).
            u64 xp0[8], xp1[8];
            #pragma unroll
            for (int u = 0; u < 4; u++) {
                const float* rowp = xrow + (size_t)(fi * 4 + u) * BC_T;
                ulonglong2 v0 = *reinterpret_cast<const ulonglong2*>(rowp);
                ulonglong2 v1 = *reinterpret_cast<const ulonglong2*>(rowp + 4);
                xp0[2 * u] = v0.x;  xp0[2 * u + 1] = v0.y;
                xp1[2 * u] = v1.x;  xp1[2 * u + 1] = v1.y;
            }

            // Accumulator init {base, tp}: lo/hi halves accumulate independent
            // partial sums; the final lo+hi folds BOTH biases for free.
            u64 a0 = pack2(base[fi].x, tp0.x);
            u64 a1 = pack2(base[fi].y, tp0.y);
            u64 a2 = pack2(base[fi].z, tp0.z);
            u64 a3 = pack2(base[fi].w, tp0.w);
            u64 b0 = pack2(base[fi].x, tp1.x);
            u64 b1 = pack2(base[fi].y, tp1.y);
            u64 b2 = pack2(base[fi].z, tp1.z);
            u64 b3 = pack2(base[fi].w, tp1.w);

            #pragma unroll
            for (int k = 0; k < 8; k++) {
                fma2(a0, xp0[k], w[k]);
                fma2(a1, xp0[k], w[8 + k]);
                fma2(a2, xp0[k], w[16 + k]);
                fma2(a3, xp0[k], w[24 + k]);
                fma2(b0, xp1[k], w[k]);
                fma2(b1, xp1[k], w[8 + k]);
                fma2(b2, xp1[k], w[16 + k]);
                fma2(b3, xp1[k], w[24 + k]);
            }

            float4 r0, r1;
            { float lo, hi; unpack2(a0, lo, hi); r0.x = lo + hi; }
            { float lo, hi; unpack2(a1, lo, hi); r0.y = lo + hi; }
            { float lo, hi; unpack2(a2, lo, hi); r0.z = lo + hi; }
            { float lo, hi; unpack2(a3, lo, hi); r0.w = lo + hi; }
            { float lo, hi; unpack2(b0, lo, hi); r1.x = lo + hi; }
            { float lo, hi; unpack2(b1, lo, hi); r1.y = lo + hi; }
            { float lo, hi; unpack2(b2, lo, hi); r1.z = lo + hi; }
            { float lo, hi; unpack2(b3, lo, hi); r1.w = lo + hi; }

            stg_cs(op_f, r0);
            stg_cs(op_f + BC_E, r1);
            op_f += BC_NT * BC_E;   // next f row (marching pointer)
        }
    }
}

extern "C" void kernel_launch(void* const* d_in, const int* in_sizes, int n_in,
                              void* d_out, int out_size)
{
    const float* x    = (const float*)d_in[0];
    const float* W    = (const float*)d_in[1];
    const float* bv   = (const float*)d_in[2];
    const float* ch   = (const float*)d_in[3];
    const float* sp   = (const float*)d_in[4];
    const float* tpos = (const float*)d_in[5];
    const float* fpos = (const float*)d_in[6];
    const int*   sidx = (const int*)d_in[7];
    float* out = (float*)d_out;

    const int Bx = in_sizes[0] / (BC_C * BC_FR * BC_T);

    dim3 grid(BC_C, Bx, 2);
    patch_embed_kernel<<<grid, 96>>>(x, W, bv, ch, sp, tpos, fpos, sidx, out);
}